// round 4
// baseline (speedup 1.0000x reference)
#include <cuda_runtime.h>
#include <math.h>

#define BATCH 2
#define SEQ 2048
#define HIDDEN 2048
#define NH 16
#define KVH 4
#define HD 128
#define MTOT (BATCH*SEQ)

// scratch (no allocation allowed -> device globals)
__device__ float g_q[MTOT*HIDDEN];
__device__ float g_k[MTOT*KVH*HD];
__device__ float g_v[MTOT*KVH*HD];
__device__ float g_ctx[MTOT*HIDDEN];

// ---------------------------------------------------------------------------
// SGEMM: C[M,N] = A[M,K] @ B[N,K]^T   (torch Linear convention)
// 128x128 tile, BK=8, 256 threads, 8x8 microtile
// ---------------------------------------------------------------------------
__global__ void __launch_bounds__(256) sgemm_abt(
    const float* __restrict__ A, const float* __restrict__ B,
    float* __restrict__ C, int M, int N, int K)
{
    __shared__ float As[8][132];
    __shared__ float Bs[8][132];
    const int tid = threadIdx.x;
    const int tx = tid & 15, ty = tid >> 4;
    const int m0 = blockIdx.y << 7, n0 = blockIdx.x << 7;
    const int lrow = tid >> 1, lk = (tid & 1) << 2;

    float acc[8][8];
#pragma unroll
    for (int i = 0; i < 8; i++)
#pragma unroll
        for (int j = 0; j < 8; j++) acc[i][j] = 0.f;

    const float* Ap = A + (size_t)(m0 + lrow) * K + lk;
    const float* Bp = B + (size_t)(n0 + lrow) * K + lk;

    for (int k0 = 0; k0 < K; k0 += 8) {
        float4 a4 = *(const float4*)(Ap + k0);
        float4 b4 = *(const float4*)(Bp + k0);
        As[lk+0][lrow] = a4.x; As[lk+1][lrow] = a4.y;
        As[lk+2][lrow] = a4.z; As[lk+3][lrow] = a4.w;
        Bs[lk+0][lrow] = b4.x; Bs[lk+1][lrow] = b4.y;
        Bs[lk+2][lrow] = b4.z; Bs[lk+3][lrow] = b4.w;
        __syncthreads();
#pragma unroll
        for (int kk = 0; kk < 8; kk++) {
            float a[8], b[8];
            *(float4*)&a[0] = *(const float4*)&As[kk][ty*8];
            *(float4*)&a[4] = *(const float4*)&As[kk][ty*8+4];
            *(float4*)&b[0] = *(const float4*)&Bs[kk][tx*8];
            *(float4*)&b[4] = *(const float4*)&Bs[kk][tx*8+4];
#pragma unroll
            for (int i = 0; i < 8; i++)
#pragma unroll
                for (int j = 0; j < 8; j++)
                    acc[i][j] += a[i]*b[j];
        }
        __syncthreads();
    }
#pragma unroll
    for (int i = 0; i < 8; i++) {
        float* Cp = C + (size_t)(m0 + ty*8 + i) * N + n0 + tx*8;
        float4 c0; c0.x=acc[i][0]; c0.y=acc[i][1]; c0.z=acc[i][2]; c0.w=acc[i][3];
        float4 c1; c1.x=acc[i][4]; c1.y=acc[i][5]; c1.z=acc[i][6]; c1.w=acc[i][7];
        *(float4*)(Cp)   = c0;
        *(float4*)(Cp+4) = c1;
    }
}

// ---------------------------------------------------------------------------
// RoPE, in-place on [B*S, nheads, HD]. Each thread handles a (d, d+64) pair.
// out[d]    = x[d]*cos[s,d]      - x[d+64]*sin[s,d]
// out[d+64] = x[d+64]*cos[s,d+64] + x[d]*sin[s,d+64]
// ---------------------------------------------------------------------------
__global__ void rope_kernel(float* __restrict__ x, const float* __restrict__ cs,
                            const float* __restrict__ sn, int nheads, int total)
{
    int idx = blockIdx.x * 256 + threadIdx.x;
    if (idx >= total) return;
    int d = idx & 63;
    int h = (idx >> 6) % nheads;
    int t = idx / (nheads << 6);      // t = b*S + s
    int s = t & (SEQ - 1);
    float* row = x + ((size_t)t * nheads + h) * HD;
    float x1 = row[d], x2 = row[d + 64];
    float c1 = cs[s*HD + d],     s1 = sn[s*HD + d];
    float c2 = cs[s*HD + d + 64], s2 = sn[s*HD + d + 64];
    row[d]      = x1 * c1 - x2 * s1;
    row[d + 64] = x2 * c2 + x1 * s2;
}

// ---------------------------------------------------------------------------
// Flash attention (causal, GQA). Br=Bc=64, D=128, fp32.
// grid (S/64, NH, B), 256 threads. Each warp owns 8 query rows (O in regs).
// ---------------------------------------------------------------------------
#define QK_STRIDE 65
#define SS_STRIDE 68
#define FLASH_SMEM ((128*QK_STRIDE*2 + 64*128 + 64*SS_STRIDE) * sizeof(float))

__global__ void __launch_bounds__(256) flash_kernel(
    const float* __restrict__ q, const float* __restrict__ k,
    const float* __restrict__ v, float* __restrict__ ctx)
{
    extern __shared__ float sm[];
    float* sQ = sm;                       // transposed [d:128][r:64], stride 65
    float* sK = sQ + 128*QK_STRIDE;       // transposed [d:128][c:64], stride 65
    float* sV = sK + 128*QK_STRIDE;       // row-major  [j:64][c:128]
    float* sS = sV + 64*128;              // [r:64][c:64], stride 68

    const int b = blockIdx.z, h = blockIdx.y, qb = blockIdx.x;
    const int kh = h >> 2;                // GROUPS = 4
    const int tid = threadIdx.x;
    const int warp = tid >> 5, lane = tid & 31;
    const int tx = tid & 15, ty = tid >> 4;

    // load Q tile (transposed store)
    const float* qbase = q + ((size_t)(b*SEQ + qb*64) * NH + h) * HD;
#pragma unroll
    for (int l = 0; l < 8; l++) {
        int idx = tid + l*256;
        int r = idx >> 5, d4 = (idx & 31) << 2;
        float4 t4 = *(const float4*)(qbase + (size_t)r * (NH*HD) + d4);
        sQ[(d4+0)*QK_STRIDE + r] = t4.x;
        sQ[(d4+1)*QK_STRIDE + r] = t4.y;
        sQ[(d4+2)*QK_STRIDE + r] = t4.z;
        sQ[(d4+3)*QK_STRIDE + r] = t4.w;
    }

    float m_r[8], l_r[8], acc[8][4];
#pragma unroll
    for (int i = 0; i < 8; i++) {
        m_r[i] = -1e30f; l_r[i] = 0.f;
        acc[i][0]=acc[i][1]=acc[i][2]=acc[i][3]=0.f;
    }

    const int grow0 = qb * 64;
    for (int jb = 0; jb <= qb; jb++) {
        __syncthreads();  // prior PV reads of sS/sV done before overwrite
        const float* kbase = k + ((size_t)(b*SEQ + jb*64) * KVH + kh) * HD;
        const float* vbase = v + ((size_t)(b*SEQ + jb*64) * KVH + kh) * HD;
#pragma unroll
        for (int l = 0; l < 8; l++) {
            int idx = tid + l*256;
            int r = idx >> 5, d4 = (idx & 31) << 2;
            float4 k4 = *(const float4*)(kbase + (size_t)r * (KVH*HD) + d4);
            sK[(d4+0)*QK_STRIDE + r] = k4.x;
            sK[(d4+1)*QK_STRIDE + r] = k4.y;
            sK[(d4+2)*QK_STRIDE + r] = k4.z;
            sK[(d4+3)*QK_STRIDE + r] = k4.w;
            float4 v4 = *(const float4*)(vbase + (size_t)r * (KVH*HD) + d4);
            *(float4*)&sV[r*128 + d4] = v4;
        }
        __syncthreads();

        // scores: 16x16 threads, 4x4 microtile each
        float sc[4][4];
#pragma unroll
        for (int i = 0; i < 4; i++)
#pragma unroll
            for (int j = 0; j < 4; j++) sc[i][j] = 0.f;
        const int r0 = ty*4, c0 = tx*4;
#pragma unroll 4
        for (int d = 0; d < 128; d++) {
            float qa[4], kb[4];
#pragma unroll
            for (int i = 0; i < 4; i++) qa[i] = sQ[d*QK_STRIDE + r0 + i];
#pragma unroll
            for (int j = 0; j < 4; j++) kb[j] = sK[d*QK_STRIDE + c0 + j];
#pragma unroll
            for (int i = 0; i < 4; i++)
#pragma unroll
                for (int j = 0; j < 4; j++)
                    sc[i][j] += qa[i]*kb[j];
        }
        const float sscale = 0.08838834764831845f;   // 1/sqrt(128)
#pragma unroll
        for (int i = 0; i < 4; i++) {
            float4 s4;
            s4.x = sc[i][0]*sscale; s4.y = sc[i][1]*sscale;
            s4.z = sc[i][2]*sscale; s4.w = sc[i][3]*sscale;
            *(float4*)&sS[(r0+i)*SS_STRIDE + c0] = s4;
        }
        __syncthreads();

        // online softmax + PV, warp w owns rows 8w..8w+7
        const bool diag = (jb == qb);
        const int col0 = jb * 64;
        const int cbase = lane * 4;
#pragma unroll
        for (int rr = 0; rr < 8; rr++) {
            int r = warp*8 + rr;
            int grow = grow0 + r;
            float s1 = sS[r*SS_STRIDE + lane];
            float s2 = sS[r*SS_STRIDE + 32 + lane];
            if (diag) {
                if (col0 + lane > grow)      s1 = -1e30f;
                if (col0 + 32 + lane > grow) s2 = -1e30f;
            }
            float mx = fmaxf(s1, s2);
#pragma unroll
            for (int o = 16; o > 0; o >>= 1)
                mx = fmaxf(mx, __shfl_xor_sync(0xffffffffu, mx, o));
            float m_new = fmaxf(m_r[rr], mx);
            float corr = __expf(m_r[rr] - m_new);
            float p1 = __expf(s1 - m_new);
            float p2 = __expf(s2 - m_new);
            float ps = p1 + p2;
#pragma unroll
            for (int o = 16; o > 0; o >>= 1)
                ps += __shfl_xor_sync(0xffffffffu, ps, o);
            l_r[rr] = l_r[rr] * corr + ps;
            m_r[rr] = m_new;
            sS[r*SS_STRIDE + lane] = p1;
            sS[r*SS_STRIDE + 32 + lane] = p2;
            acc[rr][0] *= corr; acc[rr][1] *= corr;
            acc[rr][2] *= corr; acc[rr][3] *= corr;
            __syncwarp();
#pragma unroll 4
            for (int j0 = 0; j0 < 64; j0 += 4) {
                float4 p4 = *(const float4*)&sS[r*SS_STRIDE + j0];
                float4 v0 = *(const float4*)&sV[(j0+0)*128 + cbase];
                float4 v1 = *(const float4*)&sV[(j0+1)*128 + cbase];
                float4 v2 = *(const float4*)&sV[(j0+2)*128 + cbase];
                float4 v3 = *(const float4*)&sV[(j0+3)*128 + cbase];
                acc[rr][0] += p4.x*v0.x; acc[rr][1] += p4.x*v0.y;
                acc[rr][2] += p4.x*v0.z; acc[rr][3] += p4.x*v0.w;
                acc[rr][0] += p4.y*v1.x; acc[rr][1] += p4.y*v1.y;
                acc[rr][2] += p4.y*v1.z; acc[rr][3] += p4.y*v1.w;
                acc[rr][0] += p4.z*v2.x; acc[rr][1] += p4.z*v2.y;
                acc[rr][2] += p4.z*v2.z; acc[rr][3] += p4.z*v2.w;
                acc[rr][0] += p4.w*v3.x; acc[rr][1] += p4.w*v3.y;
                acc[rr][2] += p4.w*v3.z; acc[rr][3] += p4.w*v3.w;
            }
        }
    }

    // epilogue: ctx[b, s, h*HD + d]
#pragma unroll
    for (int rr = 0; rr < 8; rr++) {
        int grow = grow0 + warp*8 + rr;
        float inv = 1.f / l_r[rr];
        float4 o4;
        o4.x = acc[rr][0]*inv; o4.y = acc[rr][1]*inv;
        o4.z = acc[rr][2]*inv; o4.w = acc[rr][3]*inv;
        float* dst = ctx + ((size_t)(b*SEQ + grow) * NH + h) * HD + lane*4;
        *(float4*)dst = o4;
    }
}

// ---------------------------------------------------------------------------
extern "C" void kernel_launch(void* const* d_in, const int* in_sizes, int n_in,
                              void* d_out, int out_size)
{
    const float* hs   = (const float*)d_in[0];
    const float* cosp = (const float*)d_in[1];
    const float* sinp = (const float*)d_in[2];
    const float* Wq   = (const float*)d_in[3];
    const float* Wk   = (const float*)d_in[4];
    const float* Wv   = (const float*)d_in[5];
    const float* Wo   = (const float*)d_in[6];
    float* out = (float*)d_out;

    float *q, *k, *v, *ctx;
    cudaGetSymbolAddress((void**)&q,   g_q);
    cudaGetSymbolAddress((void**)&k,   g_k);
    cudaGetSymbolAddress((void**)&v,   g_v);
    cudaGetSymbolAddress((void**)&ctx, g_ctx);

    const int M = MTOT;  // 4096

    // projections
    sgemm_abt<<<dim3(HIDDEN/128, M/128), 256>>>(hs, Wq, q, M, HIDDEN, HIDDEN);
    sgemm_abt<<<dim3((KVH*HD)/128, M/128), 256>>>(hs, Wk, k, M, KVH*HD, HIDDEN);
    sgemm_abt<<<dim3((KVH*HD)/128, M/128), 256>>>(hs, Wv, v, M, KVH*HD, HIDDEN);

    // RoPE on q and k
    {
        int nq = M * NH * 64;
        rope_kernel<<<(nq + 255)/256, 256>>>(q, cosp, sinp, NH, nq);
        int nk = M * KVH * 64;
        rope_kernel<<<(nk + 255)/256, 256>>>(k, cosp, sinp, KVH, nk);
    }

    // attention
    cudaFuncSetAttribute(flash_kernel, cudaFuncAttributeMaxDynamicSharedMemorySize,
                         (int)FLASH_SMEM);
    flash_kernel<<<dim3(SEQ/64, NH, BATCH), 256, FLASH_SMEM>>>(q, k, v, ctx);

    // output projection
    sgemm_abt<<<dim3(HIDDEN/128, M/128), 256>>>(ctx, Wo, out, M, HIDDEN, HIDDEN);
}

// round 6
// speedup vs baseline: 1.7221x; 1.7221x over previous
#include <cuda_runtime.h>
#include <math.h>
#include <stdint.h>

#define BATCH 2
#define SEQ 2048
#define HIDDEN 2048
#define NH 16
#define KVH 4
#define HD 128
#define MTOT (BATCH*SEQ)

// scratch (no allocation allowed -> device globals)
__device__ float g_q[MTOT*HIDDEN];
__device__ float g_k[MTOT*KVH*HD];
__device__ float g_v[MTOT*KVH*HD];
__device__ float g_ctx[MTOT*HIDDEN];
__device__ float g_hs[MTOT*HIDDEN];            // tf32-rounded hidden states
__device__ float g_wq[HIDDEN*HIDDEN];
__device__ float g_wk[KVH*HD*HIDDEN];
__device__ float g_wv[KVH*HD*HIDDEN];
__device__ float g_wo[HIDDEN*HIDDEN];

// ===========================================================================
// helpers
// ===========================================================================
__device__ __forceinline__ uint32_t smem_u32(const void* p) {
    uint32_t a;
    asm("{ .reg .u64 t; cvta.to.shared.u64 t, %1; cvt.u32.u64 %0, t; }"
        : "=r"(a) : "l"(p));
    return a;
}
__device__ __forceinline__ void cp_async16(uint32_t saddr, const void* gaddr) {
    asm volatile("cp.async.cg.shared.global [%0], [%1], 16;"
                 :: "r"(saddr), "l"(gaddr));
}
__device__ __forceinline__ void cp_commit() {
    asm volatile("cp.async.commit_group;" ::: "memory");
}
__device__ __forceinline__ void cp_wait1() {
    asm volatile("cp.async.wait_group 1;" ::: "memory");
}
__device__ __forceinline__ float tf32_round(float x) {
    uint32_t u;
    asm("cvt.rna.tf32.f32 %0, %1;" : "=r"(u) : "f"(x));
    return __uint_as_float(u);
}
// D += A*B : m16n8k8 tf32 (inputs pre-rounded to tf32, so raw bits are valid)
__device__ __forceinline__ void mma_tf32(float* d, const uint32_t* a, const uint32_t* b) {
    asm volatile(
        "mma.sync.aligned.m16n8k8.row.col.f32.tf32.tf32.f32 "
        "{%0,%1,%2,%3}, {%4,%5,%6,%7}, {%8,%9}, {%0,%1,%2,%3};"
        : "+f"(d[0]), "+f"(d[1]), "+f"(d[2]), "+f"(d[3])
        : "r"(a[0]), "r"(a[1]), "r"(a[2]), "r"(a[3]), "r"(b[0]), "r"(b[1]));
}

// ===========================================================================
// tf32 rounding pass (removes truncation bias in the MMA inputs)
// ===========================================================================
__global__ void round_tf32_kernel(float* __restrict__ dst,
                                  const float* __restrict__ src, int n4)
{
    int i = blockIdx.x * 256 + threadIdx.x;
    if (i >= n4) return;
    float4 v = ((const float4*)src)[i];
    v.x = tf32_round(v.x); v.y = tf32_round(v.y);
    v.z = tf32_round(v.z); v.w = tf32_round(v.w);
    ((float4*)dst)[i] = v;
}

// ===========================================================================
// tf32 mma.sync GEMM: C[M,N] = A[M,K] @ B[N,K]^T   (inputs pre-rounded tf32)
// CTA 128x128, BK=32, 3-stage cp.async pipeline, 8 warps (2x4 warp grid).
// M,N multiples of 128; K multiple of 32.
// ===========================================================================
#define BK 32
#define APAD 36                       // smem row stride in floats (bank-spread)
#define STAGE_FLOATS (2*128*APAD)     // A tile then B tile
#define NSTAGE 3
#define GEMM_SMEM (NSTAGE*STAGE_FLOATS*4)

__global__ void __launch_bounds__(256, 1) gemm_mma(
    const float* __restrict__ A, const float* __restrict__ B,
    float* __restrict__ C, int M, int N, int K)
{
    extern __shared__ float sm[];
    const uint32_t smb = smem_u32(sm);

    const int tid  = threadIdx.x;
    const int warp = tid >> 5, lane = tid & 31;
    const int wm = warp >> 2, wn = warp & 3;   // 2 x 4 warp grid
    const int m0 = blockIdx.y << 7, n0 = blockIdx.x << 7;
    const int q = lane >> 2, r = lane & 3;     // fragment quad-row / k-offset

    float acc[4][4][4];
#pragma unroll
    for (int i = 0; i < 4; i++)
#pragma unroll
        for (int j = 0; j < 4; j++)
            acc[i][j][0]=acc[i][j][1]=acc[i][j][2]=acc[i][j][3]=0.f;

    // per-thread cp.async slots: 4 chunks (16B) of A + 4 of B per k-tile
    int lrow[4], lch[4];
#pragma unroll
    for (int i = 0; i < 4; i++) {
        int idx = tid + i*256;           // 0..1023
        lrow[i] = idx >> 3;              // 0..127
        lch[i]  = (idx & 7) << 2;        // 0,4,..28 (floats)
    }

#define LOAD_TILE(s, kt) do {                                               \
    const uint32_t sA = smb + (uint32_t)(s)*STAGE_FLOATS*4;                 \
    const uint32_t sB = sA + 128*APAD*4;                                    \
    const int koff = (kt) * BK;                                             \
    _Pragma("unroll")                                                       \
    for (int i_ = 0; i_ < 4; i_++) {                                        \
        cp_async16(sA + (uint32_t)(lrow[i_]*APAD + lch[i_])*4,              \
                   A + (size_t)(m0 + lrow[i_]) * K + koff + lch[i_]);       \
        cp_async16(sB + (uint32_t)(lrow[i_]*APAD + lch[i_])*4,              \
                   B + (size_t)(n0 + lrow[i_]) * K + koff + lch[i_]);       \
    } } while (0)

    const int KT = K / BK;
    // prologue: stages 0,1
    LOAD_TILE(0, 0); cp_commit();
    LOAD_TILE(1, 1); cp_commit();
    cp_wait1();              // k-tile 0 resident
    __syncthreads();

    for (int kt = 0; kt < KT; kt++) {
        // issue load for kt+2 into the stage freed at end of last iteration
        const int nxt = kt + 2;
        if (nxt < KT) {
            int s = nxt - (nxt/NSTAGE)*NSTAGE;
            LOAD_TILE(s, nxt);
        }
        cp_commit();

        // compute on stage kt%3
        const int cs = kt - (kt/NSTAGE)*NSTAGE;
        const float* sA = sm + cs*STAGE_FLOATS;
        const float* sB = sA + 128*APAD;
#pragma unroll
        for (int ks = 0; ks < 4; ks++) {
            const int kk = ks * 8;
            uint32_t a[4][4], b[4][2];
#pragma unroll
            for (int i = 0; i < 4; i++) {
                const int rowb = wm*64 + i*16;
                a[i][0] = __float_as_uint(sA[(rowb+q  )*APAD + kk + r    ]);
                a[i][1] = __float_as_uint(sA[(rowb+q+8)*APAD + kk + r    ]);
                a[i][2] = __float_as_uint(sA[(rowb+q  )*APAD + kk + r + 4]);
                a[i][3] = __float_as_uint(sA[(rowb+q+8)*APAD + kk + r + 4]);
            }
#pragma unroll
            for (int j = 0; j < 4; j++) {
                const int colb = wn*32 + j*8;
                b[j][0] = __float_as_uint(sB[(colb+q)*APAD + kk + r    ]);
                b[j][1] = __float_as_uint(sB[(colb+q)*APAD + kk + r + 4]);
            }
#pragma unroll
            for (int i = 0; i < 4; i++)
#pragma unroll
                for (int j = 0; j < 4; j++)
                    mma_tf32(acc[i][j], a[i], b[j]);
        }

        cp_wait1();          // k-tile kt+1 resident
        __syncthreads();     // also fences stage reuse for next LOAD_TILE
    }

    // epilogue: c0/c1 -> (row, 2r..2r+1), c2/c3 -> (row+8, ...)
#pragma unroll
    for (int i = 0; i < 4; i++) {
        const int row = m0 + wm*64 + i*16 + q;
#pragma unroll
        for (int j = 0; j < 4; j++) {
            const int col = n0 + wn*32 + j*8 + 2*r;
            float2 lo; lo.x = acc[i][j][0]; lo.y = acc[i][j][1];
            float2 hi; hi.x = acc[i][j][2]; hi.y = acc[i][j][3];
            *(float2*)(C + (size_t)row * N + col)       = lo;
            *(float2*)(C + (size_t)(row+8) * N + col)   = hi;
        }
    }
#undef LOAD_TILE
}

// ---------------------------------------------------------------------------
// RoPE, in-place on [B*S, nheads, HD].
// ---------------------------------------------------------------------------
__global__ void rope_kernel(float* __restrict__ x, const float* __restrict__ cs,
                            const float* __restrict__ sn, int nheads, int total)
{
    int idx = blockIdx.x * 256 + threadIdx.x;
    if (idx >= total) return;
    int d = idx & 63;
    int h = (idx >> 6) % nheads;
    int t = idx / (nheads << 6);
    int s = t & (SEQ - 1);
    float* row = x + ((size_t)t * nheads + h) * HD;
    float x1 = row[d], x2 = row[d + 64];
    float c1 = cs[s*HD + d],      s1 = sn[s*HD + d];
    float c2 = cs[s*HD + d + 64], s2 = sn[s*HD + d + 64];
    row[d]      = x1 * c1 - x2 * s1;
    row[d + 64] = x2 * c2 + x1 * s2;
}

// ---------------------------------------------------------------------------
// Flash attention (causal, GQA). Br=Bc=64, D=128, fp32. Epilogue rounds ctx
// to tf32 (feeds the tf32 O-projection).
// ---------------------------------------------------------------------------
#define QK_STRIDE 65
#define SS_STRIDE 68
#define FLASH_SMEM ((128*QK_STRIDE*2 + 64*128 + 64*SS_STRIDE) * sizeof(float))

__global__ void __launch_bounds__(256) flash_kernel(
    const float* __restrict__ q, const float* __restrict__ k,
    const float* __restrict__ v, float* __restrict__ ctx)
{
    extern __shared__ float sm[];
    float* sQ = sm;
    float* sK = sQ + 128*QK_STRIDE;
    float* sV = sK + 128*QK_STRIDE;
    float* sS = sV + 64*128;

    const int b = blockIdx.z, h = blockIdx.y, qb = blockIdx.x;
    const int kh = h >> 2;
    const int tid = threadIdx.x;
    const int warp = tid >> 5, lane = tid & 31;
    const int tx = tid & 15, ty = tid >> 4;

    const float* qbase = q + ((size_t)(b*SEQ + qb*64) * NH + h) * HD;
#pragma unroll
    for (int l = 0; l < 8; l++) {
        int idx = tid + l*256;
        int r = idx >> 5, d4 = (idx & 31) << 2;
        float4 t4 = *(const float4*)(qbase + (size_t)r * (NH*HD) + d4);
        sQ[(d4+0)*QK_STRIDE + r] = t4.x;
        sQ[(d4+1)*QK_STRIDE + r] = t4.y;
        sQ[(d4+2)*QK_STRIDE + r] = t4.z;
        sQ[(d4+3)*QK_STRIDE + r] = t4.w;
    }

    float m_r[8], l_r[8], acc[8][4];
#pragma unroll
    for (int i = 0; i < 8; i++) {
        m_r[i] = -1e30f; l_r[i] = 0.f;
        acc[i][0]=acc[i][1]=acc[i][2]=acc[i][3]=0.f;
    }

    const int grow0 = qb * 64;
    for (int jb = 0; jb <= qb; jb++) {
        __syncthreads();
        const float* kbase = k + ((size_t)(b*SEQ + jb*64) * KVH + kh) * HD;
        const float* vbase = v + ((size_t)(b*SEQ + jb*64) * KVH + kh) * HD;
#pragma unroll
        for (int l = 0; l < 8; l++) {
            int idx = tid + l*256;
            int r = idx >> 5, d4 = (idx & 31) << 2;
            float4 k4 = *(const float4*)(kbase + (size_t)r * (KVH*HD) + d4);
            sK[(d4+0)*QK_STRIDE + r] = k4.x;
            sK[(d4+1)*QK_STRIDE + r] = k4.y;
            sK[(d4+2)*QK_STRIDE + r] = k4.z;
            sK[(d4+3)*QK_STRIDE + r] = k4.w;
            float4 v4 = *(const float4*)(vbase + (size_t)r * (KVH*HD) + d4);
            *(float4*)&sV[r*128 + d4] = v4;
        }
        __syncthreads();

        float sc[4][4];
#pragma unroll
        for (int i = 0; i < 4; i++)
#pragma unroll
            for (int j = 0; j < 4; j++) sc[i][j] = 0.f;
        const int r0 = ty*4, c0 = tx*4;
#pragma unroll 4
        for (int d = 0; d < 128; d++) {
            float qa[4], kb[4];
#pragma unroll
            for (int i = 0; i < 4; i++) qa[i] = sQ[d*QK_STRIDE + r0 + i];
#pragma unroll
            for (int j = 0; j < 4; j++) kb[j] = sK[d*QK_STRIDE + c0 + j];
#pragma unroll
            for (int i = 0; i < 4; i++)
#pragma unroll
                for (int j = 0; j < 4; j++)
                    sc[i][j] += qa[i]*kb[j];
        }
        const float sscale = 0.08838834764831845f;
#pragma unroll
        for (int i = 0; i < 4; i++) {
            float4 s4;
            s4.x = sc[i][0]*sscale; s4.y = sc[i][1]*sscale;
            s4.z = sc[i][2]*sscale; s4.w = sc[i][3]*sscale;
            *(float4*)&sS[(r0+i)*SS_STRIDE + c0] = s4;
        }
        __syncthreads();

        const bool diag = (jb == qb);
        const int col0 = jb * 64;
        const int cbase = lane * 4;
#pragma unroll
        for (int rr = 0; rr < 8; rr++) {
            int r = warp*8 + rr;
            int grow = grow0 + r;
            float s1 = sS[r*SS_STRIDE + lane];
            float s2 = sS[r*SS_STRIDE + 32 + lane];
            if (diag) {
                if (col0 + lane > grow)      s1 = -1e30f;
                if (col0 + 32 + lane > grow) s2 = -1e30f;
            }
            float mx = fmaxf(s1, s2);
#pragma unroll
            for (int o = 16; o > 0; o >>= 1)
                mx = fmaxf(mx, __shfl_xor_sync(0xffffffffu, mx, o));
            float m_new = fmaxf(m_r[rr], mx);
            float corr = __expf(m_r[rr] - m_new);
            float p1 = __expf(s1 - m_new);
            float p2 = __expf(s2 - m_new);
            float ps = p1 + p2;
#pragma unroll
            for (int o = 16; o > 0; o >>= 1)
                ps += __shfl_xor_sync(0xffffffffu, ps, o);
            l_r[rr] = l_r[rr] * corr + ps;
            m_r[rr] = m_new;
            sS[r*SS_STRIDE + lane] = p1;
            sS[r*SS_STRIDE + 32 + lane] = p2;
            acc[rr][0] *= corr; acc[rr][1] *= corr;
            acc[rr][2] *= corr; acc[rr][3] *= corr;
            __syncwarp();
#pragma unroll 4
            for (int j0 = 0; j0 < 64; j0 += 4) {
                float4 p4 = *(const float4*)&sS[r*SS_STRIDE + j0];
                float4 v0 = *(const float4*)&sV[(j0+0)*128 + cbase];
                float4 v1 = *(const float4*)&sV[(j0+1)*128 + cbase];
                float4 v2 = *(const float4*)&sV[(j0+2)*128 + cbase];
                float4 v3 = *(const float4*)&sV[(j0+3)*128 + cbase];
                acc[rr][0] += p4.x*v0.x; acc[rr][1] += p4.x*v0.y;
                acc[rr][2] += p4.x*v0.z; acc[rr][3] += p4.x*v0.w;
                acc[rr][0] += p4.y*v1.x; acc[rr][1] += p4.y*v1.y;
                acc[rr][2] += p4.y*v1.z; acc[rr][3] += p4.y*v1.w;
                acc[rr][0] += p4.z*v2.x; acc[rr][1] += p4.z*v2.y;
                acc[rr][2] += p4.z*v2.z; acc[rr][3] += p4.z*v2.w;
                acc[rr][0] += p4.w*v3.x; acc[rr][1] += p4.w*v3.y;
                acc[rr][2] += p4.w*v3.z; acc[rr][3] += p4.w*v3.w;
            }
        }
    }

    // epilogue: round to tf32 so the tf32 O-projection sees pre-rounded input
#pragma unroll
    for (int rr = 0; rr < 8; rr++) {
        int grow = grow0 + warp*8 + rr;
        float inv = 1.f / l_r[rr];
        float4 o4;
        o4.x = tf32_round(acc[rr][0]*inv); o4.y = tf32_round(acc[rr][1]*inv);
        o4.z = tf32_round(acc[rr][2]*inv); o4.w = tf32_round(acc[rr][3]*inv);
        float* dst = ctx + ((size_t)(b*SEQ + grow) * NH + h) * HD + lane*4;
        *(float4*)dst = o4;
    }
}

// ---------------------------------------------------------------------------
extern "C" void kernel_launch(void* const* d_in, const int* in_sizes, int n_in,
                              void* d_out, int out_size)
{
    const float* hs   = (const float*)d_in[0];
    const float* cosp = (const float*)d_in[1];
    const float* sinp = (const float*)d_in[2];
    const float* Wq   = (const float*)d_in[3];
    const float* Wk   = (const float*)d_in[4];
    const float* Wv   = (const float*)d_in[5];
    const float* Wo   = (const float*)d_in[6];
    float* out = (float*)d_out;

    float *q, *k, *v, *ctx, *hs_t, *wq, *wk, *wv, *wo;
    cudaGetSymbolAddress((void**)&q,    g_q);
    cudaGetSymbolAddress((void**)&k,    g_k);
    cudaGetSymbolAddress((void**)&v,    g_v);
    cudaGetSymbolAddress((void**)&ctx,  g_ctx);
    cudaGetSymbolAddress((void**)&hs_t, g_hs);
    cudaGetSymbolAddress((void**)&wq,   g_wq);
    cudaGetSymbolAddress((void**)&wk,   g_wk);
    cudaGetSymbolAddress((void**)&wv,   g_wv);
    cudaGetSymbolAddress((void**)&wo,   g_wo);

    cudaFuncSetAttribute(gemm_mma, cudaFuncAttributeMaxDynamicSharedMemorySize,
                         (int)GEMM_SMEM);
    cudaFuncSetAttribute(flash_kernel, cudaFuncAttributeMaxDynamicSharedMemorySize,
                         (int)FLASH_SMEM);

    const int M = MTOT;  // 4096

    // tf32 pre-rounding (removes truncation bias in tensor-core inputs)
    {
        int n4;
        n4 = M*HIDDEN/4;          round_tf32_kernel<<<(n4+255)/256,256>>>(hs_t, hs, n4);
        n4 = HIDDEN*HIDDEN/4;     round_tf32_kernel<<<(n4+255)/256,256>>>(wq, Wq, n4);
        n4 = KVH*HD*HIDDEN/4;     round_tf32_kernel<<<(n4+255)/256,256>>>(wk, Wk, n4);
        n4 = KVH*HD*HIDDEN/4;     round_tf32_kernel<<<(n4+255)/256,256>>>(wv, Wv, n4);
        n4 = HIDDEN*HIDDEN/4;     round_tf32_kernel<<<(n4+255)/256,256>>>(wo, Wo, n4);
    }

    // projections (mma.sync tf32)
    gemm_mma<<<dim3(HIDDEN/128, M/128), 256, GEMM_SMEM>>>(hs_t, wq, q, M, HIDDEN, HIDDEN);
    gemm_mma<<<dim3((KVH*HD)/128, M/128), 256, GEMM_SMEM>>>(hs_t, wk, k, M, KVH*HD, HIDDEN);
    gemm_mma<<<dim3((KVH*HD)/128, M/128), 256, GEMM_SMEM>>>(hs_t, wv, v, M, KVH*HD, HIDDEN);

    // RoPE on q and k
    {
        int nq = M * NH * 64;
        rope_kernel<<<(nq + 255)/256, 256>>>(q, cosp, sinp, NH, nq);
        int nk = M * KVH * 64;
        rope_kernel<<<(nk + 255)/256, 256>>>(k, cosp, sinp, KVH, nk);
    }

    // attention (fp32 flash, epilogue rounds ctx to tf32)
    flash_kernel<<<dim3(SEQ/64, NH, BATCH), 256, FLASH_SMEM>>>(q, k, v, ctx);

    // output projection (mma.sync tf32)
    gemm_mma<<<dim3(HIDDEN/128, M/128), 256, GEMM_SMEM>>>(ctx, wo, out, M, HIDDEN, HIDDEN);
}

// round 7
// speedup vs baseline: 3.3634x; 1.9531x over previous
#include <cuda_runtime.h>
#include <math.h>
#include <stdint.h>

#define BATCH 2
#define SEQ 2048
#define HIDDEN 2048
#define NH 16
#define KVH 4
#define HD 128
#define MTOT (BATCH*SEQ)

// scratch (no allocation allowed -> device globals)
__device__ float g_q[MTOT*HIDDEN];
__device__ float g_k[MTOT*KVH*HD];
__device__ float g_v[MTOT*KVH*HD];
__device__ float g_ctx[MTOT*HIDDEN];
__device__ float g_hs[MTOT*HIDDEN];            // tf32-rounded hidden states
__device__ float g_wq[HIDDEN*HIDDEN];
__device__ float g_wk[KVH*HD*HIDDEN];
__device__ float g_wv[KVH*HD*HIDDEN];
__device__ float g_wo[HIDDEN*HIDDEN];

// ===========================================================================
// helpers
// ===========================================================================
__device__ __forceinline__ uint32_t smem_u32(const void* p) {
    uint32_t a;
    asm("{ .reg .u64 t; cvta.to.shared.u64 t, %1; cvt.u32.u64 %0, t; }"
        : "=r"(a) : "l"(p));
    return a;
}
__device__ __forceinline__ void cp_async16(uint32_t saddr, const void* gaddr) {
    asm volatile("cp.async.cg.shared.global [%0], [%1], 16;"
                 :: "r"(saddr), "l"(gaddr));
}
__device__ __forceinline__ void cp_commit() {
    asm volatile("cp.async.commit_group;" ::: "memory");
}
__device__ __forceinline__ void cp_wait1() {
    asm volatile("cp.async.wait_group 1;" ::: "memory");
}
__device__ __forceinline__ float tf32_round(float x) {
    uint32_t u;
    asm("cvt.rna.tf32.f32 %0, %1;" : "=r"(u) : "f"(x));
    return __uint_as_float(u);
}
// D += A*B : m16n8k8 tf32 (inputs pre-rounded to tf32, so raw bits are valid)
__device__ __forceinline__ void mma_tf32(float* d, const uint32_t* a, const uint32_t* b) {
    asm volatile(
        "mma.sync.aligned.m16n8k8.row.col.f32.tf32.tf32.f32 "
        "{%0,%1,%2,%3}, {%4,%5,%6,%7}, {%8,%9}, {%0,%1,%2,%3};"
        : "+f"(d[0]), "+f"(d[1]), "+f"(d[2]), "+f"(d[3])
        : "r"(a[0]), "r"(a[1]), "r"(a[2]), "r"(a[3]), "r"(b[0]), "r"(b[1]));
}

// ===========================================================================
// fused tf32 rounding pass over all 5 input buffers (one launch)
// ===========================================================================
#define N4_HS  (MTOT*HIDDEN/4)
#define N4_WQ  (HIDDEN*HIDDEN/4)
#define N4_WKV (KVH*HD*HIDDEN/4)
#define N4_TOT (N4_HS + 2*N4_WQ + 2*N4_WKV)

__global__ void round5_kernel(
    const float* __restrict__ hs, const float* __restrict__ wq,
    const float* __restrict__ wk, const float* __restrict__ wv,
    const float* __restrict__ wo,
    float* __restrict__ dhs, float* __restrict__ dwq,
    float* __restrict__ dwk, float* __restrict__ dwv,
    float* __restrict__ dwo)
{
    int i = blockIdx.x * 256 + threadIdx.x;
    if (i >= N4_TOT) return;
    const float* src; float* dst; int j = i;
    if (j < N4_HS)        { src = hs; dst = dhs; }
    else if ((j -= N4_HS) < N4_WQ)  { src = wq; dst = dwq; }
    else if ((j -= N4_WQ) < N4_WKV) { src = wk; dst = dwk; }
    else if ((j -= N4_WKV) < N4_WKV){ src = wv; dst = dwv; }
    else { j -= N4_WKV; src = wo; dst = dwo; }
    float4 v = ((const float4*)src)[j];
    v.x = tf32_round(v.x); v.y = tf32_round(v.y);
    v.z = tf32_round(v.z); v.w = tf32_round(v.w);
    ((float4*)dst)[j] = v;
}

// ===========================================================================
// tf32 mma.sync GEMM: C[M,N] = A[M,K] @ B[N,K]^T   (inputs pre-rounded tf32)
// CTA 128x128, BK=32, 3-stage cp.async pipeline, 8 warps (2x4 warp grid).
// ===========================================================================
#define BK 32
#define APAD 36
#define STAGE_FLOATS (2*128*APAD)
#define NSTAGE 3
#define GEMM_SMEM (NSTAGE*STAGE_FLOATS*4)

__global__ void __launch_bounds__(256, 1) gemm_mma(
    const float* __restrict__ A, const float* __restrict__ B,
    float* __restrict__ C, int M, int N, int K)
{
    extern __shared__ float sm[];
    const uint32_t smb = smem_u32(sm);

    const int tid  = threadIdx.x;
    const int warp = tid >> 5, lane = tid & 31;
    const int wm = warp >> 2, wn = warp & 3;
    const int m0 = blockIdx.y << 7, n0 = blockIdx.x << 7;
    const int q = lane >> 2, r = lane & 3;

    float acc[4][4][4];
#pragma unroll
    for (int i = 0; i < 4; i++)
#pragma unroll
        for (int j = 0; j < 4; j++)
            acc[i][j][0]=acc[i][j][1]=acc[i][j][2]=acc[i][j][3]=0.f;

    int lrow[4], lch[4];
#pragma unroll
    for (int i = 0; i < 4; i++) {
        int idx = tid + i*256;
        lrow[i] = idx >> 3;
        lch[i]  = (idx & 7) << 2;
    }

#define LOAD_TILE(s, kt) do {                                               \
    const uint32_t sA = smb + (uint32_t)(s)*STAGE_FLOATS*4;                 \
    const uint32_t sB = sA + 128*APAD*4;                                    \
    const int koff = (kt) * BK;                                             \
    _Pragma("unroll")                                                       \
    for (int i_ = 0; i_ < 4; i_++) {                                        \
        cp_async16(sA + (uint32_t)(lrow[i_]*APAD + lch[i_])*4,              \
                   A + (size_t)(m0 + lrow[i_]) * K + koff + lch[i_]);       \
        cp_async16(sB + (uint32_t)(lrow[i_]*APAD + lch[i_])*4,              \
                   B + (size_t)(n0 + lrow[i_]) * K + koff + lch[i_]);       \
    } } while (0)

    const int KT = K / BK;
    LOAD_TILE(0, 0); cp_commit();
    LOAD_TILE(1, 1); cp_commit();
    cp_wait1();
    __syncthreads();

    for (int kt = 0; kt < KT; kt++) {
        const int nxt = kt + 2;
        if (nxt < KT) {
            int s = nxt - (nxt/NSTAGE)*NSTAGE;
            LOAD_TILE(s, nxt);
        }
        cp_commit();

        const int cs = kt - (kt/NSTAGE)*NSTAGE;
        const float* sA = sm + cs*STAGE_FLOATS;
        const float* sB = sA + 128*APAD;
#pragma unroll
        for (int ks = 0; ks < 4; ks++) {
            const int kk = ks * 8;
            uint32_t a[4][4], b[4][2];
#pragma unroll
            for (int i = 0; i < 4; i++) {
                const int rowb = wm*64 + i*16;
                a[i][0] = __float_as_uint(sA[(rowb+q  )*APAD + kk + r    ]);
                a[i][1] = __float_as_uint(sA[(rowb+q+8)*APAD + kk + r    ]);
                a[i][2] = __float_as_uint(sA[(rowb+q  )*APAD + kk + r + 4]);
                a[i][3] = __float_as_uint(sA[(rowb+q+8)*APAD + kk + r + 4]);
            }
#pragma unroll
            for (int j = 0; j < 4; j++) {
                const int colb = wn*32 + j*8;
                b[j][0] = __float_as_uint(sB[(colb+q)*APAD + kk + r    ]);
                b[j][1] = __float_as_uint(sB[(colb+q)*APAD + kk + r + 4]);
            }
#pragma unroll
            for (int i = 0; i < 4; i++)
#pragma unroll
                for (int j = 0; j < 4; j++)
                    mma_tf32(acc[i][j], a[i], b[j]);
        }

        cp_wait1();
        __syncthreads();
    }

#pragma unroll
    for (int i = 0; i < 4; i++) {
        const int row = m0 + wm*64 + i*16 + q;
#pragma unroll
        for (int j = 0; j < 4; j++) {
            const int col = n0 + wn*32 + j*8 + 2*r;
            float2 lo; lo.x = acc[i][j][0]; lo.y = acc[i][j][1];
            float2 hi; hi.x = acc[i][j][2]; hi.y = acc[i][j][3];
            *(float2*)(C + (size_t)row * N + col)       = lo;
            *(float2*)(C + (size_t)(row+8) * N + col)   = hi;
        }
    }
#undef LOAD_TILE
}

// ---------------------------------------------------------------------------
// fused RoPE on q and k (one launch), in-place
// ---------------------------------------------------------------------------
#define ROPE_NQ (MTOT*NH*64)
#define ROPE_NK (MTOT*KVH*64)

__global__ void rope_fused_kernel(float* __restrict__ xq, float* __restrict__ xk,
                                  const float* __restrict__ cs,
                                  const float* __restrict__ sn)
{
    int idx = blockIdx.x * 256 + threadIdx.x;
    float* x; int nheads;
    if (idx < ROPE_NQ) { x = xq; nheads = NH; }
    else if (idx < ROPE_NQ + ROPE_NK) { idx -= ROPE_NQ; x = xk; nheads = KVH; }
    else return;
    int d = idx & 63;
    int h = (idx >> 6) % nheads;
    int t = idx / (nheads << 6);
    int s = t & (SEQ - 1);
    float* row = x + ((size_t)t * nheads + h) * HD;
    float x1 = row[d], x2 = row[d + 64];
    float c1 = cs[s*HD + d],      s1 = sn[s*HD + d];
    float c2 = cs[s*HD + d + 64], s2 = sn[s*HD + d + 64];
    row[d]      = x1 * c1 - x2 * s1;
    row[d + 64] = x2 * c2 + x1 * s2;
}

// ---------------------------------------------------------------------------
// Flash attention with mma.sync tf32 (causal, GQA). Br=Bc=64, D=128.
// 8 warps: QK warp grid 2x4 (tile 32x16), PV warp grid 2x4 (tile 32x32).
// Softmax stays scalar fp32 on sS; per-row corr published via smem.
// ---------------------------------------------------------------------------
#define QKP 132                 // sQ/sK row stride (floats)
#define VTP 68                  // sVt row stride
#define SSP 68                  // sS row stride
#define SQ_OFF  0
#define SK_OFF  (64*QKP)
#define SVT_OFF (SK_OFF + 64*QKP)
#define SS_OFF  (SVT_OFF + 128*VTP)
#define SCR_OFF (SS_OFF + 64*SSP)
#define FLASH_FLOATS (SCR_OFF + 64)
#define FLASH_SMEM (FLASH_FLOATS*4)

__global__ void __launch_bounds__(256, 1) flash_mma_kernel(
    const float* __restrict__ q, const float* __restrict__ k,
    const float* __restrict__ v, float* __restrict__ ctx)
{
    extern __shared__ float sm[];
    float* sQ   = sm + SQ_OFF;
    float* sK   = sm + SK_OFF;
    float* sVt  = sm + SVT_OFF;
    float* sS   = sm + SS_OFF;
    float* scorr= sm + SCR_OFF;

    const int b = blockIdx.z, h = blockIdx.y;
    const int qb = (int)gridDim.x - 1 - (int)blockIdx.x;  // long CTAs first
    const int kh = h >> 2;
    const int tid = threadIdx.x;
    const int warp = tid >> 5, lane = tid & 31;
    const int wm = warp >> 2, wn = warp & 3;      // 2 x 4 warp grid
    const int qd = lane >> 2, r4 = lane & 3;      // fragment quad / k-offset

    // ---- load Q tile (row-major, tf32-rounded) ----
    const float* qbase = q + ((size_t)(b*SEQ + qb*64) * NH + h) * HD;
#pragma unroll
    for (int l = 0; l < 8; l++) {
        int idx = tid + l*256;
        int row = idx >> 5, c4 = (idx & 31) << 2;
        float4 t4 = *(const float4*)(qbase + (size_t)row * (NH*HD) + c4);
        t4.x = tf32_round(t4.x); t4.y = tf32_round(t4.y);
        t4.z = tf32_round(t4.z); t4.w = tf32_round(t4.w);
        *(float4*)&sQ[row*QKP + c4] = t4;
    }

    // softmax state (warp w owns rows 8w..8w+7)
    float m_r[8], l_r[8];
#pragma unroll
    for (int i = 0; i < 8; i++) { m_r[i] = -1e30f; l_r[i] = 0.f; }

    // O accumulators: warp tile 32x32 at (wm*32, wn*32); 2 m-tiles x 4 n-tiles
    float oacc[2][4][4];
#pragma unroll
    for (int i = 0; i < 2; i++)
#pragma unroll
        for (int j = 0; j < 4; j++)
            oacc[i][j][0]=oacc[i][j][1]=oacc[i][j][2]=oacc[i][j][3]=0.f;

    const int grow0 = qb * 64;
    const float sscale = 0.08838834764831845f;   // 1/sqrt(128)

    for (int jb = 0; jb <= qb; jb++) {
        __syncthreads();   // prior PV done with sS/sVt/scorr; K/V tiles free
        const float* kbase = k + ((size_t)(b*SEQ + jb*64) * KVH + kh) * HD;
        const float* vbase = v + ((size_t)(b*SEQ + jb*64) * KVH + kh) * HD;
#pragma unroll
        for (int l = 0; l < 8; l++) {
            int idx = tid + l*256;
            int row = idx >> 5, c4 = (idx & 31) << 2;
            float4 k4 = *(const float4*)(kbase + (size_t)row * (KVH*HD) + c4);
            k4.x = tf32_round(k4.x); k4.y = tf32_round(k4.y);
            k4.z = tf32_round(k4.z); k4.w = tf32_round(k4.w);
            *(float4*)&sK[row*QKP + c4] = k4;
            float4 v4 = *(const float4*)(vbase + (size_t)row * (KVH*HD) + c4);
            sVt[(c4+0)*VTP + row] = tf32_round(v4.x);
            sVt[(c4+1)*VTP + row] = tf32_round(v4.y);
            sVt[(c4+2)*VTP + row] = tf32_round(v4.z);
            sVt[(c4+3)*VTP + row] = tf32_round(v4.w);
        }
        __syncthreads();

        // ---- scores: warp tile 32x16 at (wm*32, wn*16), K-loop 16 steps ----
        float sc[2][2][4];
#pragma unroll
        for (int i = 0; i < 2; i++)
#pragma unroll
            for (int j = 0; j < 2; j++)
                sc[i][j][0]=sc[i][j][1]=sc[i][j][2]=sc[i][j][3]=0.f;
#pragma unroll
        for (int ks = 0; ks < 16; ks++) {
            const int kk = ks * 8;
            uint32_t a[2][4], bf[2][2];
#pragma unroll
            for (int i = 0; i < 2; i++) {
                const int rowb = wm*32 + i*16;
                a[i][0] = __float_as_uint(sQ[(rowb+qd  )*QKP + kk + r4    ]);
                a[i][1] = __float_as_uint(sQ[(rowb+qd+8)*QKP + kk + r4    ]);
                a[i][2] = __float_as_uint(sQ[(rowb+qd  )*QKP + kk + r4 + 4]);
                a[i][3] = __float_as_uint(sQ[(rowb+qd+8)*QKP + kk + r4 + 4]);
            }
#pragma unroll
            for (int j = 0; j < 2; j++) {
                const int colb = wn*16 + j*8;
                bf[j][0] = __float_as_uint(sK[(colb+qd)*QKP + kk + r4    ]);
                bf[j][1] = __float_as_uint(sK[(colb+qd)*QKP + kk + r4 + 4]);
            }
#pragma unroll
            for (int i = 0; i < 2; i++)
#pragma unroll
                for (int j = 0; j < 2; j++)
                    mma_tf32(sc[i][j], a[i], bf[j]);
        }
        // store scaled scores to sS
#pragma unroll
        for (int i = 0; i < 2; i++) {
            const int row = wm*32 + i*16 + qd;
#pragma unroll
            for (int j = 0; j < 2; j++) {
                const int col = wn*16 + j*8 + 2*r4;
                float2 lo; lo.x = sc[i][j][0]*sscale; lo.y = sc[i][j][1]*sscale;
                float2 hi; hi.x = sc[i][j][2]*sscale; hi.y = sc[i][j][3]*sscale;
                *(float2*)&sS[row*SSP + col]     = lo;
                *(float2*)&sS[(row+8)*SSP + col] = hi;
            }
        }
        __syncthreads();

        // ---- softmax (scalar fp32), warp w owns rows 8w..8w+7 ----
        const bool diag = (jb == qb);
        const int col0 = jb * 64;
#pragma unroll
        for (int rr = 0; rr < 8; rr++) {
            int row = warp*8 + rr;
            int grow = grow0 + row;
            float s1 = sS[row*SSP + lane];
            float s2 = sS[row*SSP + 32 + lane];
            if (diag) {
                if (col0 + lane > grow)      s1 = -1e30f;
                if (col0 + 32 + lane > grow) s2 = -1e30f;
            }
            float mx = fmaxf(s1, s2);
#pragma unroll
            for (int o = 16; o > 0; o >>= 1)
                mx = fmaxf(mx, __shfl_xor_sync(0xffffffffu, mx, o));
            float m_new = fmaxf(m_r[rr], mx);
            float corr = __expf(m_r[rr] - m_new);
            float p1 = __expf(s1 - m_new);
            float p2 = __expf(s2 - m_new);
            float ps = p1 + p2;
#pragma unroll
            for (int o = 16; o > 0; o >>= 1)
                ps += __shfl_xor_sync(0xffffffffu, ps, o);
            l_r[rr] = l_r[rr] * corr + ps;
            m_r[rr] = m_new;
            sS[row*SSP + lane]      = tf32_round(p1);
            sS[row*SSP + 32 + lane] = tf32_round(p2);
            if (lane == 0) scorr[row] = corr;
        }
        __syncthreads();

        // ---- PV: warp tile 32x32 at (wm*32, wn*32), K-loop 8 steps ----
        float cr0[2], cr1[2];
#pragma unroll
        for (int i = 0; i < 2; i++) {
            const int row = wm*32 + i*16 + qd;
            cr0[i] = scorr[row];
            cr1[i] = scorr[row+8];
        }
#pragma unroll
        for (int i = 0; i < 2; i++)
#pragma unroll
            for (int j = 0; j < 4; j++) {
                oacc[i][j][0] *= cr0[i]; oacc[i][j][1] *= cr0[i];
                oacc[i][j][2] *= cr1[i]; oacc[i][j][3] *= cr1[i];
            }
#pragma unroll
        for (int ks = 0; ks < 8; ks++) {
            const int kk = ks * 8;
            uint32_t a[2][4], bf[4][2];
#pragma unroll
            for (int i = 0; i < 2; i++) {
                const int rowb = wm*32 + i*16;
                a[i][0] = __float_as_uint(sS[(rowb+qd  )*SSP + kk + r4    ]);
                a[i][1] = __float_as_uint(sS[(rowb+qd+8)*SSP + kk + r4    ]);
                a[i][2] = __float_as_uint(sS[(rowb+qd  )*SSP + kk + r4 + 4]);
                a[i][3] = __float_as_uint(sS[(rowb+qd+8)*SSP + kk + r4 + 4]);
            }
#pragma unroll
            for (int j = 0; j < 4; j++) {
                const int colb = wn*32 + j*8;
                bf[j][0] = __float_as_uint(sVt[(colb+qd)*VTP + kk + r4    ]);
                bf[j][1] = __float_as_uint(sVt[(colb+qd)*VTP + kk + r4 + 4]);
            }
#pragma unroll
            for (int i = 0; i < 2; i++)
#pragma unroll
                for (int j = 0; j < 4; j++)
                    mma_tf32(oacc[i][j], a[i], bf[j]);
        }
    }

    // publish 1/l per row (reuse scorr after all PV reads are done)
    __syncthreads();
#pragma unroll
    for (int rr = 0; rr < 8; rr++)
        if (lane == 0) scorr[warp*8 + rr] = 1.f / l_r[rr];
    __syncthreads();

    // epilogue: write O (tf32-rounded for the tf32 O-projection)
#pragma unroll
    for (int i = 0; i < 2; i++) {
        const int row = wm*32 + i*16 + qd;
        const float inv0 = scorr[row], inv1 = scorr[row+8];
        float* d0 = ctx + ((size_t)(b*SEQ + grow0 + row  ) * NH + h) * HD;
        float* d1 = ctx + ((size_t)(b*SEQ + grow0 + row+8) * NH + h) * HD;
#pragma unroll
        for (int j = 0; j < 4; j++) {
            const int col = wn*32 + j*8 + 2*r4;
            float2 lo, hi;
            lo.x = tf32_round(oacc[i][j][0]*inv0);
            lo.y = tf32_round(oacc[i][j][1]*inv0);
            hi.x = tf32_round(oacc[i][j][2]*inv1);
            hi.y = tf32_round(oacc[i][j][3]*inv1);
            *(float2*)(d0 + col) = lo;
            *(float2*)(d1 + col) = hi;
        }
    }
}

// ---------------------------------------------------------------------------
extern "C" void kernel_launch(void* const* d_in, const int* in_sizes, int n_in,
                              void* d_out, int out_size)
{
    const float* hs   = (const float*)d_in[0];
    const float* cosp = (const float*)d_in[1];
    const float* sinp = (const float*)d_in[2];
    const float* Wq   = (const float*)d_in[3];
    const float* Wk   = (const float*)d_in[4];
    const float* Wv   = (const float*)d_in[5];
    const float* Wo   = (const float*)d_in[6];
    float* out = (float*)d_out;

    float *q, *k, *v, *ctx, *hs_t, *wq, *wk, *wv, *wo;
    cudaGetSymbolAddress((void**)&q,    g_q);
    cudaGetSymbolAddress((void**)&k,    g_k);
    cudaGetSymbolAddress((void**)&v,    g_v);
    cudaGetSymbolAddress((void**)&ctx,  g_ctx);
    cudaGetSymbolAddress((void**)&hs_t, g_hs);
    cudaGetSymbolAddress((void**)&wq,   g_wq);
    cudaGetSymbolAddress((void**)&wk,   g_wk);
    cudaGetSymbolAddress((void**)&wv,   g_wv);
    cudaGetSymbolAddress((void**)&wo,   g_wo);

    cudaFuncSetAttribute(gemm_mma, cudaFuncAttributeMaxDynamicSharedMemorySize,
                         (int)GEMM_SMEM);
    cudaFuncSetAttribute(flash_mma_kernel, cudaFuncAttributeMaxDynamicSharedMemorySize,
                         (int)FLASH_SMEM);

    const int M = MTOT;  // 4096

    // 1) fused tf32 pre-rounding of all inputs
    round5_kernel<<<(N4_TOT + 255)/256, 256>>>(hs, Wq, Wk, Wv, Wo,
                                               hs_t, wq, wk, wv, wo);

    // 2-4) projections (mma.sync tf32)
    gemm_mma<<<dim3(HIDDEN/128, M/128), 256, GEMM_SMEM>>>(hs_t, wq, q, M, HIDDEN, HIDDEN);
    gemm_mma<<<dim3((KVH*HD)/128, M/128), 256, GEMM_SMEM>>>(hs_t, wk, k, M, KVH*HD, HIDDEN);
    gemm_mma<<<dim3((KVH*HD)/128, M/128), 256, GEMM_SMEM>>>(hs_t, wv, v, M, KVH*HD, HIDDEN);

    // 5) fused RoPE on q and k
    {
        int tot = ROPE_NQ + ROPE_NK;
        rope_fused_kernel<<<(tot + 255)/256, 256>>>(q, k, cosp, sinp);
    }

    // 6) attention (mma.sync tf32 flash)
    flash_mma_kernel<<<dim3(SEQ/64, NH, BATCH), 256, FLASH_SMEM>>>(q, k, v, ctx);

    // 7) output projection (mma.sync tf32)
    gemm_mma<<<dim3(HIDDEN/128, M/128), 256, GEMM_SMEM>>>(ctx, wo, out, M, HIDDEN, HIDDEN);
}